// round 5
// baseline (speedup 1.0000x reference)
#include <cuda_runtime.h>

typedef unsigned long long ull;

#define BATCH 1024
#define TLEN  200
#define DDIM  128
#define HDIM  128
#define NXC   384
#define MROWS (BATCH * TLEN)

__device__ float g_xproj[(size_t)MROWS * NXC];

// ---------- packed f32x2 helpers ----------
__device__ __forceinline__ ull dup2(float v) {
    ull r; asm("mov.b64 %0,{%1,%1};" : "=l"(r) : "f"(v)); return r;
}
__device__ __forceinline__ ull pack2(float x, float y) {
    ull r; asm("mov.b64 %0,{%1,%2};" : "=l"(r) : "f"(x), "f"(y)); return r;
}
__device__ __forceinline__ float2 unpack2(ull v) {
    float2 f; asm("mov.b64 {%0,%1},%2;" : "=f"(f.x), "=f"(f.y) : "l"(v)); return f;
}
__device__ __forceinline__ void ffma2(ull &d, ull a, ull b) {
    asm("fma.rn.f32x2 %0,%1,%2,%0;" : "+l"(d) : "l"(a), "l"(b));
}
__device__ __forceinline__ ull addf2(ull a, ull b) {
    ull r; asm("add.rn.f32x2 %0,%1,%2;" : "=l"(r) : "l"(a), "l"(b)); return r;
}
__device__ __forceinline__ float tanhap(float x) {
    float r; asm("tanh.approx.f32 %0,%1;" : "=f"(r) : "f"(x)); return r;
}
__device__ __forceinline__ float sigap(float x) {
    return fmaf(tanhap(0.5f * x), 0.5f, 0.5f);
}

// =====================================================================
// Phase 1 (unchanged R2 version): xproj = X @ Wx + bias.
// =====================================================================
__global__ void __launch_bounds__(256, 2) dien_xproj_kernel(
    const float* __restrict__ X, const int* __restrict__ seqlen,
    const float* __restrict__ Wg, const float* __restrict__ bg,
    const float* __restrict__ Wc, const float* __restrict__ bc)
{
    extern __shared__ float sm[];
    float* xsT = sm;
    float* ws  = sm + 64 * 132;

    const int tid = threadIdx.x;
    const int r0  = blockIdx.y * 128;
    const int ct  = blockIdx.x;

    __shared__ int anyv;
    if (tid == 0) anyv = 0;
    __syncthreads();
    if (tid < 128) {
        int r = r0 + tid;
        int b = r / TLEN, t = r - b * TLEN;
        if (t < seqlen[b]) anyv = 1;
    }
    __syncthreads();
    if (!anyv) return;

    const int tx = tid & 15;
    const int ty = tid >> 4;

    ull acc[8][4];
    {
        const float* bias = (ct < 2) ? (bg + ct * 128 + tx * 8) : (bc + tx * 8);
        #pragma unroll
        for (int p = 0; p < 4; p++) {
            ull bp = pack2(bias[2 * p], bias[2 * p + 1]);
            #pragma unroll
            for (int i = 0; i < 8; i++) acc[i][p] = bp;
        }
    }

    const float4* X4 = (const float4*)(X + (size_t)r0 * DDIM);

    for (int c = 0; c < 2; c++) {
        #pragma unroll
        for (int idx = tid; idx < 2048; idx += 256) {
            int k4 = idx >> 7;
            int r  = idx & 127;
            float4 v = X4[(size_t)r * 32 + c * 16 + k4];
            int kb = k4 * 4;
            xsT[(kb + 0) * 132 + r] = v.x;
            xsT[(kb + 1) * 132 + r] = v.y;
            xsT[(kb + 2) * 132 + r] = v.z;
            xsT[(kb + 3) * 132 + r] = v.w;
        }
        if (ct < 2) {
            const float4* W4 = (const float4*)Wg;
            #pragma unroll
            for (int idx = tid; idx < 2048; idx += 256) {
                int k = idx >> 5, c4 = idx & 31;
                *(float4*)&ws[k * 128 + c4 * 4] = W4[(c * 64 + k) * 64 + ct * 32 + c4];
            }
        } else {
            const float4* W4 = (const float4*)Wc;
            #pragma unroll
            for (int idx = tid; idx < 2048; idx += 256) {
                int k = idx >> 5, c4 = idx & 31;
                *(float4*)&ws[k * 128 + c4 * 4] = W4[(c * 64 + k) * 32 + c4];
            }
        }
        __syncthreads();

        const float4*     a4 = (const float4*)xsT;
        const ulonglong2* b2 = (const ulonglong2*)ws;

        #pragma unroll 4
        for (int k = 0; k < 64; k++) {
            float4 av0 = a4[k * 33 + ty * 2];
            float4 av1 = a4[k * 33 + ty * 2 + 1];
            ulonglong2 b01 = b2[k * 32 + tx * 2];
            ulonglong2 b23 = b2[k * 32 + tx * 2 + 1];
            ull A[8];
            A[0] = dup2(av0.x); A[1] = dup2(av0.y); A[2] = dup2(av0.z); A[3] = dup2(av0.w);
            A[4] = dup2(av1.x); A[5] = dup2(av1.y); A[6] = dup2(av1.z); A[7] = dup2(av1.w);
            #pragma unroll
            for (int i = 0; i < 8; i++) {
                ffma2(acc[i][0], A[i], b01.x);
                ffma2(acc[i][1], A[i], b01.y);
                ffma2(acc[i][2], A[i], b23.x);
                ffma2(acc[i][3], A[i], b23.y);
            }
        }
        __syncthreads();
    }

    #pragma unroll
    for (int i = 0; i < 8; i++) {
        size_t r = (size_t)(r0 + ty * 8 + i);
        float2 p0 = unpack2(acc[i][0]);
        float2 p1 = unpack2(acc[i][1]);
        float2 p2 = unpack2(acc[i][2]);
        float2 p3 = unpack2(acc[i][3]);
        float* dst = &g_xproj[r * NXC + ct * 128 + tx * 8];
        ((float4*)dst)[0] = make_float4(p0.x, p0.y, p1.x, p1.y);
        ((float4*)dst)[1] = make_float4(p2.x, p2.y, p3.x, p3.y);
    }
}

// =====================================================================
// Phase 2: fully thread-local GRU. 128 CTAs x 512 thr, 8 rows each.
// Thread (jc, P): gate lanes=(r,u) with packed (wr,wu) smem weights;
// cand lanes=(k-even,k-odd) partial sums, folded locally.
// No reductions, no staging, 2 barriers/step.
// =====================================================================
#define WGP_ROW 130     // ull per jc row (128 + 2 pad)
#define WCT_ROW 132     // floats per jc row
#define H_ROW   132     // floats per batch-row

__global__ void __launch_bounds__(512, 1) dien_gru_kernel(
    const float* __restrict__ Wg, const float* __restrict__ Wc,
    const int* __restrict__ seqlen, float* __restrict__ out)
{
    extern __shared__ char smraw[];
    ull*   wgP  = (ull*)smraw;                        // [128 jc][130] (wr,wu) pairs  133120 B
    float* wcT  = (float*)(smraw + 133120);           // [128 jc][132]                 67584 B
    float* hsm  = (float*)(smraw + 133120 + 67584);   // [8 row][132]                   4224 B
    float* rhsm = hsm + 8 * H_ROW;                    // [8 row][132]                   4224 B

    const int tid   = threadIdx.x;
    const int rows0 = blockIdx.x * 8;
    const int lane  = tid & 31;
    const int w     = tid >> 5;
    const int jl    = lane & 7;
    const int P     = lane >> 3;          // row pair 0..3
    const int jc    = w * 8 + jl;         // column 0..127
    const int rowa  = 2 * P, rowb = 2 * P + 1;

    // ---- preamble: pack gate weights (wr,wu), transpose cand weights ----
    for (int i = tid; i < 128 * 128; i += 512) {
        int k = i >> 7, j = i & 127;
        float wr = Wg[(size_t)(128 + k) * 256 + j];
        float wu = Wg[(size_t)(128 + k) * 256 + j + 128];
        wgP[j * WGP_ROW + k] = pack2(wr, wu);
        wcT[j * WCT_ROW + k] = Wc[(size_t)(128 + k) * 128 + j];
    }
    for (int i = tid; i < 8 * H_ROW; i += 512) hsm[i] = 0.0f;

    const int sqa = seqlen[rows0 + rowa];
    const int sqb = seqlen[rows0 + rowb];
    int maxseq = 0;
    #pragma unroll
    for (int i = 0; i < 8; i++) maxseq = max(maxseq, seqlen[rows0 + i]);
    __syncthreads();

    const ulonglong2* wg2 = (const ulonglong2*)(wgP + jc * WGP_ROW);
    const ulonglong2* wc2 = (const ulonglong2*)(wcT + jc * WCT_ROW);
    const float4*     ha4 = (const float4*)(hsm  + rowa * H_ROW);
    const float4*     hb4 = (const float4*)(hsm  + rowb * H_ROW);
    const ulonglong2* ra2 = (const ulonglong2*)(rhsm + rowa * H_ROW);
    const ulonglong2* rb2 = (const ulonglong2*)(rhsm + rowb * H_ROW);

    const float* xa = g_xproj + (size_t)(rows0 + rowa) * TLEN * NXC + jc;
    const float* xb = g_xproj + (size_t)(rows0 + rowb) * TLEN * NXC + jc;
    float* outa = out + (size_t)(rows0 + rowa) * TLEN * HDIM + jc;
    float* outb = out + (size_t)(rows0 + rowb) * TLEN * HDIM + jc;

    for (int t = 0; t < maxseq; t++) {
        // prefetch x-projections (consumed after the GEMV loops)
        const float* x0 = xa + (size_t)t * NXC;
        const float* x1 = xb + (size_t)t * NXC;
        float xra = x0[0], xua = x0[128], xca = x0[256];
        float xrb = x1[0], xub = x1[128], xcb = x1[256];

        // ---- gate GEMV: lanes = (r,u); rows a,b; 128 k ----
        ull aa0 = 0, aa1 = 0, ab0 = 0, ab1 = 0;
        #pragma unroll
        for (int i = 0; i < 32; i++) {
            ulonglong2 wa = wg2[2 * i];
            ulonglong2 wb = wg2[2 * i + 1];
            float4 hA = ha4[i];
            float4 hB = hb4[i];
            ffma2(aa0, dup2(hA.x), wa.x); ffma2(aa1, dup2(hA.y), wa.y);
            ffma2(ab0, dup2(hB.x), wa.x); ffma2(ab1, dup2(hB.y), wa.y);
            ffma2(aa0, dup2(hA.z), wb.x); ffma2(aa1, dup2(hA.w), wb.y);
            ffma2(ab0, dup2(hB.z), wb.x); ffma2(ab1, dup2(hB.w), wb.y);
        }
        float2 Za = unpack2(addf2(aa0, aa1));   // (zr, zu) row a
        float2 Zb = unpack2(addf2(ab0, ab1));
        float r_a = sigap(Za.x + xra), u_a = sigap(Za.y + xua);
        float r_b = sigap(Zb.x + xrb), u_b = sigap(Zb.y + xub);
        float Hoa = hsm[rowa * H_ROW + jc];
        float Hob = hsm[rowb * H_ROW + jc];
        rhsm[rowa * H_ROW + jc] = r_a * Hoa;
        rhsm[rowb * H_ROW + jc] = r_b * Hob;
        __syncthreads();

        // ---- cand GEMV: lanes = k-parity partials; rows a,b ----
        ull ca0 = 0, ca1 = 0, cb0 = 0, cb1 = 0;
        #pragma unroll
        for (int i = 0; i < 32; i++) {
            ulonglong2 wc = wc2[i];     // (k4i,k4i+1),(k4i+2,k4i+3)
            ulonglong2 ra = ra2[i];
            ulonglong2 rb = rb2[i];
            ffma2(ca0, ra.x, wc.x); ffma2(ca1, ra.y, wc.y);
            ffma2(cb0, rb.x, wc.x); ffma2(cb1, rb.y, wc.y);
        }
        float2 Fa = unpack2(addf2(ca0, ca1));
        float2 Fb = unpack2(addf2(cb0, cb1));
        float c_a = tanhap(Fa.x + Fa.y + xca);
        float c_b = tanhap(Fb.x + Fb.y + xcb);
        float hna = fmaf(u_a, Hoa - c_a, c_a);   // u*h + (1-u)*c
        float hnb = fmaf(u_b, Hob - c_b, c_b);
        bool va = t < sqa, vb = t < sqb;
        hsm[rowa * H_ROW + jc] = va ? hna : Hoa;
        hsm[rowb * H_ROW + jc] = vb ? hnb : Hob;
        if (va) outa[(size_t)t * HDIM] = hna;
        if (vb) outb[(size_t)t * HDIM] = hnb;
        __syncthreads();
    }
}

// =====================================================================
extern "C" void kernel_launch(void* const* d_in, const int* in_sizes, int n_in,
                              void* d_out, int out_size)
{
    const float* X   = (const float*)d_in[0];
    const int*   seq = (const int*)  d_in[1];
    const float* Wg  = (const float*)d_in[2];
    const float* bg  = (const float*)d_in[3];
    const float* Wc  = (const float*)d_in[4];
    const float* bc  = (const float*)d_in[5];
    float* out = (float*)d_out;
    (void)in_sizes; (void)n_in;

    const int SMEM1 = (64 * 132 + 64 * 128) * 4;              // 66560 B
    const int SMEM2 = 133120 + 67584 + 2 * 8 * H_ROW * 4;     // 209152 B
    cudaFuncSetAttribute(dien_xproj_kernel, cudaFuncAttributeMaxDynamicSharedMemorySize, SMEM1);
    cudaFuncSetAttribute(dien_gru_kernel,   cudaFuncAttributeMaxDynamicSharedMemorySize, SMEM2);

    cudaMemsetAsync(d_out, 0, (size_t)out_size * sizeof(float));

    dim3 g1(3, MROWS / 128);
    dien_xproj_kernel<<<g1, 256, SMEM1>>>(X, seq, Wg, bg, Wc, bc);
    dien_gru_kernel<<<BATCH / 8, 512, SMEM2>>>(Wg, Wc, seq, out);
}